// round 1
// baseline (speedup 1.0000x reference)
#include <cuda_runtime.h>
#include <math.h>

#define BB 16
#define NN 4096
#define SS 1024
#define KK 32
#define NPT (BB*SS*KK)      /* 524288 points after grouping */
#define C1 64
#define C2 64
#define C3 128
#define NB1 (NPT/64)        /* 8192  blocks in layer1 */
#define NB2 (NPT/32)        /* 16384 blocks in layer2 */
#define NB3 (NPT/32)        /* 16384 blocks in layer3 */

// ---------------- scratch (device globals; no runtime allocation) ----------
__device__ float g_newxyz[BB*SS*3];
__device__ int   g_gidx[NPT];
__device__ float g_buf1[NPT*C1];          // 134 MB  pre-activation layer1
__device__ float g_buf2[NPT*C2];          // 134 MB  pre-activation layer2
__device__ float g_buf3[NPT*C3];          // 256 MB  pre-activation layer3
__device__ float g_p1s[C1*NB1], g_p1q[C1*NB1];
__device__ float g_p2s[C2*NB2], g_p2q[C2*NB2];
__device__ float g_p3s[C3*NB3], g_p3q[C3*NB3];
__device__ float g_sc1[C1], g_sh1[C1];
__device__ float g_sc2[C2], g_sh2[C2];
__device__ float g_sc3[C3], g_sh3[C3];

// ---------------------------------------------------------------------------
// 1) Farthest point sampling. One block per batch; dist kept in registers.
//    Arithmetic replicated without FMA contraction to bit-match the reference.
//    Also emits new_xyz and the transposed xyz_query output.
// ---------------------------------------------------------------------------
__global__ __launch_bounds__(256) void fps_kernel(const float* __restrict__ xyz,
                                                  float* __restrict__ out)
{
    const int b = blockIdx.x;
    const int t = threadIdx.x;
    const int T = 256;
    const int PPT = NN / T;                 // 16 points per thread
    const float* xb = xyz + (size_t)b*3*NN;

    float px[PPT], py[PPT], pz[PPT], dist[PPT];
#pragma unroll
    for (int j = 0; j < PPT; j++) {
        int p = t + j*T;
        px[j] = xb[p];
        py[j] = xb[NN + p];
        pz[j] = xb[2*NN + p];
        dist[j] = 1e10f;
    }

    __shared__ float swv[8];
    __shared__ int   swi[8];
    __shared__ int   s_far;

    const int lane = t & 31;
    const int w    = t >> 5;
    int far = 0;

    for (int i = 0; i < SS; i++) {
        float cx = xb[far];
        float cy = xb[NN + far];
        float cz = xb[2*NN + far];
        if (t == 0) {
            g_newxyz[(b*SS + i)*3 + 0] = cx;
            g_newxyz[(b*SS + i)*3 + 1] = cy;
            g_newxyz[(b*SS + i)*3 + 2] = cz;
            out[b*3*SS + 0*SS + i] = cx;
            out[b*3*SS + 1*SS + i] = cy;
            out[b*3*SS + 2*SS + i] = cz;
        }

        float bv = -1.0f; int bi = 0;
#pragma unroll
        for (int j = 0; j < PPT; j++) {
            float dx = __fsub_rn(px[j], cx);
            float dy = __fsub_rn(py[j], cy);
            float dz = __fsub_rn(pz[j], cz);
            float d  = __fadd_rn(__fadd_rn(__fmul_rn(dx,dx), __fmul_rn(dy,dy)),
                                 __fmul_rn(dz,dz));
            float nd = fminf(dist[j], d);
            dist[j] = nd;
            if (nd > bv) { bv = nd; bi = t + j*T; }   // strict > keeps lowest j
        }
        // warp argmax, ties -> smaller index
#pragma unroll
        for (int off = 16; off > 0; off >>= 1) {
            float ov = __shfl_down_sync(0xffffffffu, bv, off);
            int   oi = __shfl_down_sync(0xffffffffu, bi, off);
            if (ov > bv || (ov == bv && oi < bi)) { bv = ov; bi = oi; }
        }
        if (lane == 0) { swv[w] = bv; swi[w] = bi; }
        __syncthreads();
        if (t == 0) {
            float Bv = swv[0]; int Bi = swi[0];
#pragma unroll
            for (int ww = 1; ww < 8; ww++) {
                float ov = swv[ww]; int oi = swi[ww];
                if (ov > Bv || (ov == Bv && oi < Bi)) { Bv = ov; Bi = oi; }
            }
            s_far = Bi;
        }
        __syncthreads();
        far = s_far;
    }
}

// ---------------------------------------------------------------------------
// 2) Ball query: one warp per query point. Ordered first-K selection via
//    ballot/popc; pad with the smallest in-radius index (matches sort+fill).
// ---------------------------------------------------------------------------
__global__ __launch_bounds__(256) void ballquery_kernel(const float* __restrict__ xyz)
{
    const int warp_global = (blockIdx.x * blockDim.x + threadIdx.x) >> 5;
    const int lane = threadIdx.x & 31;
    if (warp_global >= BB*SS) return;
    const int q = warp_global;
    const int b = q >> 10;
    const float* xb = xyz + (size_t)b*3*NN;
    const float cx = g_newxyz[q*3 + 0];
    const float cy = g_newxyz[q*3 + 1];
    const float cz = g_newxyz[q*3 + 2];
    const float R2 = 0.16f;  // float(0.4*0.4) after weak-type cast

    int cnt = 0;
    int first = 0;
    for (int base = 0; base < NN; base += 32) {
        int p = base + lane;
        float dx = __fsub_rn(xb[p],        cx);
        float dy = __fsub_rn(xb[NN + p],   cy);
        float dz = __fsub_rn(xb[2*NN + p], cz);
        float d  = __fadd_rn(__fadd_rn(__fmul_rn(dx,dx), __fmul_rn(dy,dy)),
                             __fmul_rn(dz,dz));
        bool in = !(d > R2);
        unsigned mask = __ballot_sync(0xffffffffu, in);
        if (cnt == 0 && mask) first = base + __ffs(mask) - 1;
        if (in) {
            int slot = cnt + __popc(mask & ((1u << lane) - 1u));
            if (slot < KK) g_gidx[q*KK + slot] = p;
        }
        cnt += __popc(mask);
        if (cnt >= KK) break;
    }
    if (cnt < KK) {
        for (int slot = cnt + lane; slot < KK; slot += 32)
            g_gidx[q*KK + slot] = first;
    }
}

// ---------------------------------------------------------------------------
// 3) Layer1: gather + concat + 6->64 matmul, write pre-activation + stats.
//    Block = 64 points; threads = 64 channels x 4 point-groups.
// ---------------------------------------------------------------------------
__global__ __launch_bounds__(256) void layer1_kernel(const float* __restrict__ xyz,
                                                     const float* __restrict__ pts,
                                                     const float* __restrict__ W1,
                                                     const float* __restrict__ b1)
{
    const int t = threadIdx.x;
    const int base = blockIdx.x * 64;
    __shared__ float sIn[64*6];
    __shared__ float sW[64*7];
    __shared__ float rs[4][64], rq[4][64];

    for (int idx = t; idx < 64*6; idx += 256) {
        int pt = idx / 6, c = idx % 6;
        int pglob = base + pt;
        int q = pglob >> 5;       // query id
        int bq = q >> 10;         // batch
        int gi = g_gidx[pglob];
        float v;
        if (c < 3) v = __fsub_rn(xyz[(size_t)bq*3*NN + c*NN + gi], g_newxyz[q*3 + c]);
        else       v = pts[(size_t)bq*3*NN + (c-3)*NN + gi];
        sIn[pt*6 + c] = v;
    }
    for (int idx = t; idx < 64*6; idx += 256) {
        int o = idx / 6, c = idx % 6;
        sW[o*7 + c] = W1[o*6 + c];
    }
    __syncthreads();

    const int o  = t & 63;
    const int pg = t >> 6;
    float bo = b1[o];
    float acc[16];
#pragma unroll
    for (int i = 0; i < 16; i++) acc[i] = bo;
#pragma unroll
    for (int c = 0; c < 6; c++) {
        float wv = sW[o*7 + c];
#pragma unroll
        for (int i = 0; i < 16; i++)
            acc[i] = fmaf(sIn[(pg*16 + i)*6 + c], wv, acc[i]);
    }
    float ls = 0.f, lq2 = 0.f;
#pragma unroll
    for (int i = 0; i < 16; i++) {
        float v = acc[i];
        g_buf1[(size_t)(base + pg*16 + i)*C1 + o] = v;
        ls += v; lq2 += v*v;
    }
    rs[pg][o] = ls; rq[pg][o] = lq2;
    __syncthreads();
    if (t < 64) {
        g_p1s[t*NB1 + blockIdx.x] = rs[0][t] + rs[1][t] + rs[2][t] + rs[3][t];
        g_p1q[t*NB1 + blockIdx.x] = rq[0][t] + rq[1][t] + rq[2][t] + rq[3][t];
    }
}

// ---------------------------------------------------------------------------
// Finalize BN stats for one layer (one block per channel, deterministic).
// ---------------------------------------------------------------------------
__global__ __launch_bounds__(256) void finalize_kernel(const float* __restrict__ gma,
                                                       const float* __restrict__ bet,
                                                       int layer)
{
    const float* ps; const float* pq; float* sc; float* sh; int NB;
    if (layer == 0)      { ps = g_p1s; pq = g_p1q; sc = g_sc1; sh = g_sh1; NB = NB1; }
    else if (layer == 1) { ps = g_p2s; pq = g_p2q; sc = g_sc2; sh = g_sh2; NB = NB2; }
    else                 { ps = g_p3s; pq = g_p3q; sc = g_sc3; sh = g_sh3; NB = NB3; }

    const int ch = blockIdx.x, t = threadIdx.x;
    __shared__ double sa[256], sb[256];
    double a = 0.0, b2 = 0.0;
    for (int i = t; i < NB; i += 256) {
        a  += (double)ps[ch*NB + i];
        b2 += (double)pq[ch*NB + i];
    }
    sa[t] = a; sb[t] = b2;
    __syncthreads();
    for (int off = 128; off > 0; off >>= 1) {
        if (t < off) { sa[t] += sa[t + off]; sb[t] += sb[t + off]; }
        __syncthreads();
    }
    if (t == 0) {
        const double n = (double)NPT;
        double mean = sa[0] / n;
        double var  = sb[0] / n - mean*mean;
        double s    = (double)gma[ch] / sqrt(var + 1e-5);
        sc[ch] = (float)s;
        sh[ch] = (float)((double)bet[ch] - mean*s);
    }
}

// ---------------------------------------------------------------------------
// 4) Layer2: apply BN1+ReLU on the fly, 64->64 matmul, stats.
//    Block = 32 points; threads = 64 channels x 4 groups of 8 points.
// ---------------------------------------------------------------------------
__global__ __launch_bounds__(256) void layer2_kernel(const float* __restrict__ W2,
                                                     const float* __restrict__ b2)
{
    const int t = threadIdx.x;
    const int base = blockIdx.x * 32;
    __shared__ float sIn[32*64];
    __shared__ float sW[64*65];
    __shared__ float rs[4][64], rq[4][64];

    for (int idx = t; idx < 32*64; idx += 256) {
        int c = idx & 63;
        float v = g_buf1[(size_t)base*C1 + idx];
        sIn[idx] = fmaxf(fmaf(v, g_sc1[c], g_sh1[c]), 0.f);
    }
    for (int idx = t; idx < 64*64; idx += 256) {
        int o = idx >> 6, c = idx & 63;
        sW[o*65 + c] = W2[idx];
    }
    __syncthreads();

    const int o  = t & 63;
    const int pg = t >> 6;
    float bo = b2[o];
    float acc[8];
#pragma unroll
    for (int i = 0; i < 8; i++) acc[i] = bo;
#pragma unroll
    for (int c = 0; c < 64; c++) {
        float wv = sW[o*65 + c];
#pragma unroll
        for (int i = 0; i < 8; i++)
            acc[i] = fmaf(sIn[(pg*8 + i)*64 + c], wv, acc[i]);
    }
    float ls = 0.f, lq2 = 0.f;
#pragma unroll
    for (int i = 0; i < 8; i++) {
        float v = acc[i];
        g_buf2[(size_t)(base + pg*8 + i)*C2 + o] = v;
        ls += v; lq2 += v*v;
    }
    rs[pg][o] = ls; rq[pg][o] = lq2;
    __syncthreads();
    if (t < 64) {
        g_p2s[t*NB2 + blockIdx.x] = rs[0][t] + rs[1][t] + rs[2][t] + rs[3][t];
        g_p2q[t*NB2 + blockIdx.x] = rq[0][t] + rq[1][t] + rq[2][t] + rq[3][t];
    }
}

// ---------------------------------------------------------------------------
// 5) Layer3: BN2+ReLU on the fly, 64->128 matmul, stats.
//    Block = 32 points; threads = 128 channels x 2 groups of 16 points.
// ---------------------------------------------------------------------------
__global__ __launch_bounds__(256) void layer3_kernel(const float* __restrict__ W3,
                                                     const float* __restrict__ b3)
{
    const int t = threadIdx.x;
    const int base = blockIdx.x * 32;
    __shared__ float sIn[32*64];
    __shared__ float sW[128*65];
    __shared__ float rs[2][128], rq[2][128];

    for (int idx = t; idx < 32*64; idx += 256) {
        int c = idx & 63;
        float v = g_buf2[(size_t)base*C2 + idx];
        sIn[idx] = fmaxf(fmaf(v, g_sc2[c], g_sh2[c]), 0.f);
    }
    for (int idx = t; idx < 128*64; idx += 256) {
        int o = idx >> 6, c = idx & 63;
        sW[o*65 + c] = W3[idx];
    }
    __syncthreads();

    const int o  = t & 127;
    const int pg = t >> 7;
    float bo = b3[o];
    float acc[16];
#pragma unroll
    for (int i = 0; i < 16; i++) acc[i] = bo;
#pragma unroll
    for (int c = 0; c < 64; c++) {
        float wv = sW[o*65 + c];
#pragma unroll
        for (int i = 0; i < 16; i++)
            acc[i] = fmaf(sIn[(pg*16 + i)*64 + c], wv, acc[i]);
    }
    float ls = 0.f, lq2 = 0.f;
#pragma unroll
    for (int i = 0; i < 16; i++) {
        float v = acc[i];
        g_buf3[(size_t)(base + pg*16 + i)*C3 + o] = v;
        ls += v; lq2 += v*v;
    }
    rs[pg][o] = ls; rq[pg][o] = lq2;
    __syncthreads();
    if (t < 128) {
        g_p3s[t*NB3 + blockIdx.x] = rs[0][t] + rs[1][t];
        g_p3q[t*NB3 + blockIdx.x] = rq[0][t] + rq[1][t];
    }
}

// ---------------------------------------------------------------------------
// 6) BN3+ReLU + max over k, transposed write of new_points.
// ---------------------------------------------------------------------------
__global__ __launch_bounds__(256) void maxpool_kernel(float* __restrict__ out)
{
    const int gid = blockIdx.x * 256 + threadIdx.x;   // [0, B*S*128)
    const int o = gid & 127;
    const int q = gid >> 7;
    const float sc = g_sc3[o];
    const float sh = g_sh3[o];
    const float* p = g_buf3 + (size_t)q*KK*C3 + o;
    float m = -3.0e38f;
#pragma unroll
    for (int kk = 0; kk < KK; kk++)
        m = fmaxf(m, fmaf(p[kk*C3], sc, sh));
    m = fmaxf(m, 0.f);                 // relu then max == max then relu
    const int b = q >> 10;
    const int s = q & 1023;
    out[BB*3*SS + (size_t)b*C3*SS + o*SS + s] = m;
}

// ---------------------------------------------------------------------------
extern "C" void kernel_launch(void* const* d_in, const int* in_sizes, int n_in,
                              void* d_out, int out_size)
{
    const float* xyz = (const float*)d_in[0];   // [B,3,N]
    const float* pts = (const float*)d_in[1];   // [B,3,N]
    const float* W1  = (const float*)d_in[2];
    const float* b1  = (const float*)d_in[3];
    const float* g1  = (const float*)d_in[4];
    const float* be1 = (const float*)d_in[5];
    const float* W2  = (const float*)d_in[6];
    const float* b2  = (const float*)d_in[7];
    const float* g2  = (const float*)d_in[8];
    const float* be2 = (const float*)d_in[9];
    const float* W3  = (const float*)d_in[10];
    const float* b3  = (const float*)d_in[11];
    const float* g3  = (const float*)d_in[12];
    const float* be3 = (const float*)d_in[13];
    float* out = (float*)d_out;

    fps_kernel<<<BB, 256>>>(xyz, out);
    ballquery_kernel<<<(BB*SS*32)/256, 256>>>(xyz);
    layer1_kernel<<<NB1, 256>>>(xyz, pts, W1, b1);
    finalize_kernel<<<C1, 256>>>(g1, be1, 0);
    layer2_kernel<<<NB2, 256>>>(W2, b2);
    finalize_kernel<<<C2, 256>>>(g2, be2, 1);
    layer3_kernel<<<NB3, 256>>>(W3, b3);
    finalize_kernel<<<C3, 256>>>(g3, be3, 2);
    maxpool_kernel<<<(BB*SS*C3)/256, 256>>>(out);
}

// round 2
// speedup vs baseline: 1.1775x; 1.1775x over previous
#include <cuda_runtime.h>
#include <math.h>

#define BB 16
#define NN 4096
#define SS 1024
#define KK 32
#define NPT (BB*SS*KK)      /* 524288 grouped points */
#define NT  (NPT/128)       /* 4096 tiles of 128 points */
#define C1 64
#define C2 64
#define C3 128

// ---------------- scratch (device globals; no runtime allocation) ----------
__device__ float g_newxyz[BB*SS*3];
__device__ int   g_gidx[NPT];
__device__ __align__(16) float g_buf1[(size_t)NPT*C1];   // [tile][ch64][pt128]
__device__ __align__(16) float g_buf2[(size_t)NPT*C2];   // [tile][ch64][pt128]
__device__ __align__(16) float g_maxpre[BB*SS*C3];       // [q][ch] pre-BN maxima (8MB)
__device__ float g_p1s[C1*NT], g_p1q[C1*NT];
__device__ float g_p2s[C2*NT], g_p2q[C2*NT];
__device__ float g_p3s[C3*NT], g_p3q[C3*NT];
__device__ float g_sc1[C1], g_sh1[C1];
__device__ float g_sc2[C2], g_sh2[C2];
__device__ float g_sc3[C3], g_sh3[C3];

// ---------------- packed f32x2 helpers (bit-exact: two independent fp32) ---
__device__ __forceinline__ unsigned long long pack2(float lo, float hi) {
    unsigned long long r;
    asm("mov.b64 %0, {%1,%2};" : "=l"(r) : "f"(lo), "f"(hi));
    return r;
}
__device__ __forceinline__ void unpk(unsigned long long v, float& lo, float& hi) {
    asm("mov.b64 {%0,%1}, %2;" : "=f"(lo), "=f"(hi) : "l"(v));
}
__device__ __forceinline__ unsigned long long fma2(unsigned long long a,
                                                   unsigned long long b,
                                                   unsigned long long c) {
    unsigned long long d;
    asm("fma.rn.f32x2 %0, %1, %2, %3;" : "=l"(d) : "l"(a), "l"(b), "l"(c));
    return d;
}

// ---------------------------------------------------------------------------
// 1) Farthest point sampling. One block per batch; dist in registers.
//    Non-FMA arithmetic preserved (argmax sequence must match reference).
//    redux.sync for the warp argmax (bits of non-negative floats monotonic).
// ---------------------------------------------------------------------------
__global__ __launch_bounds__(256) void fps_kernel(const float* __restrict__ xyz,
                                                  float* __restrict__ out)
{
    const int b = blockIdx.x;
    const int t = threadIdx.x;
    const int T = 256;
    const int PPT = NN / T;                 // 16 points per thread
    const float* xb = xyz + (size_t)b*3*NN;

    float px[PPT], py[PPT], pz[PPT], dist[PPT];
#pragma unroll
    for (int j = 0; j < PPT; j++) {
        int p = t + j*T;
        px[j] = xb[p];
        py[j] = xb[NN + p];
        pz[j] = xb[2*NN + p];
        dist[j] = 1e10f;
    }

    __shared__ unsigned swb[8];
    __shared__ int      swi[8];
    __shared__ int      s_far;

    const int lane = t & 31;
    const int w    = t >> 5;
    int far = 0;

    for (int i = 0; i < SS; i++) {
        float cx = xb[far];
        float cy = xb[NN + far];
        float cz = xb[2*NN + far];
        if (t == 0) {
            g_newxyz[(b*SS + i)*3 + 0] = cx;
            g_newxyz[(b*SS + i)*3 + 1] = cy;
            g_newxyz[(b*SS + i)*3 + 2] = cz;
            out[b*3*SS + 0*SS + i] = cx;
            out[b*3*SS + 1*SS + i] = cy;
            out[b*3*SS + 2*SS + i] = cz;
        }

        float bv = -1.0f; int bi = 0;
#pragma unroll
        for (int j = 0; j < PPT; j++) {
            float dx = __fsub_rn(px[j], cx);
            float dy = __fsub_rn(py[j], cy);
            float dz = __fsub_rn(pz[j], cz);
            float d  = __fadd_rn(__fadd_rn(__fmul_rn(dx,dx), __fmul_rn(dy,dy)),
                                 __fmul_rn(dz,dz));
            float nd = fminf(dist[j], d);
            dist[j] = nd;
            if (nd > bv) { bv = nd; bi = t + j*T; }   // strict > keeps lowest j
        }
        // warp argmax via redux (bv >= 0 here -> bit pattern monotonic)
        unsigned bits = __float_as_uint(bv);
        unsigned wmax = __reduce_max_sync(0xffffffffu, bits);
        int cand = (bits == wmax) ? bi : 0x7fffffff;
        int wmin = __reduce_min_sync(0xffffffffu, cand);
        if (lane == 0) { swb[w] = wmax; swi[w] = wmin; }
        __syncthreads();
        if (t < 8) {
            unsigned b8 = swb[t]; int i8 = swi[t];
            unsigned m8 = __reduce_max_sync(0x000000ffu, b8);
            int c8 = (b8 == m8) ? i8 : 0x7fffffff;
            int f8 = __reduce_min_sync(0x000000ffu, c8);
            if (t == 0) s_far = f8;
        }
        __syncthreads();
        far = s_far;
    }
}

// ---------------------------------------------------------------------------
// 2) Ball query: one warp per query point (unchanged, verified correct).
// ---------------------------------------------------------------------------
__global__ __launch_bounds__(256) void ballquery_kernel(const float* __restrict__ xyz)
{
    const int warp_global = (blockIdx.x * blockDim.x + threadIdx.x) >> 5;
    const int lane = threadIdx.x & 31;
    if (warp_global >= BB*SS) return;
    const int q = warp_global;
    const int b = q >> 10;
    const float* xb = xyz + (size_t)b*3*NN;
    const float cx = g_newxyz[q*3 + 0];
    const float cy = g_newxyz[q*3 + 1];
    const float cz = g_newxyz[q*3 + 2];
    const float R2 = 0.16f;

    int cnt = 0;
    int first = 0;
    for (int base = 0; base < NN; base += 32) {
        int p = base + lane;
        float dx = __fsub_rn(xb[p],        cx);
        float dy = __fsub_rn(xb[NN + p],   cy);
        float dz = __fsub_rn(xb[2*NN + p], cz);
        float d  = __fadd_rn(__fadd_rn(__fmul_rn(dx,dx), __fmul_rn(dy,dy)),
                             __fmul_rn(dz,dz));
        bool in = !(d > R2);
        unsigned mask = __ballot_sync(0xffffffffu, in);
        if (cnt == 0 && mask) first = base + __ffs(mask) - 1;
        if (in) {
            int slot = cnt + __popc(mask & ((1u << lane) - 1u));
            if (slot < KK) g_gidx[q*KK + slot] = p;
        }
        cnt += __popc(mask);
        if (cnt >= KK) break;
    }
    if (cnt < KK) {
        for (int slot = cnt + lane; slot < KK; slot += 32)
            g_gidx[q*KK + slot] = first;
    }
}

// ---------------------------------------------------------------------------
// 3) Layer1: gather + concat + 6->64 matmul. Output in [tile][ch][pt] layout
//    so layers 2/3 load conflict-free. Block = 128-pt tile, 256 threads.
// ---------------------------------------------------------------------------
__global__ __launch_bounds__(256) void layer1_kernel(const float* __restrict__ xyz,
                                                     const float* __restrict__ pts,
                                                     const float* __restrict__ W1,
                                                     const float* __restrict__ b1)
{
    const int t = threadIdx.x;
    const int tile = blockIdx.x;
    const int base = tile * 128;
    __shared__ float sIn[128*6];
    __shared__ float sW[64*8];
    __shared__ float rs[4][64], rq[4][64];

    for (int idx = t; idx < 128*6; idx += 256) {
        int pt = idx / 6, c = idx % 6;
        int pglob = base + pt;
        int q = pglob >> 5;
        int bq = q >> 10;
        int gi = g_gidx[pglob];
        float v;
        if (c < 3) v = __fsub_rn(xyz[(size_t)bq*3*NN + c*NN + gi], g_newxyz[q*3 + c]);
        else       v = pts[(size_t)bq*3*NN + (c-3)*NN + gi];
        sIn[pt*6 + c] = v;
    }
    for (int idx = t; idx < 64*6; idx += 256) {
        int o = idx / 6, c = idx % 6;
        sW[o*8 + c] = W1[o*6 + c];
    }
    __syncthreads();

    const int o  = t & 63;
    const int pg = t >> 6;          // 4 groups of 32 points
    float bo = b1[o];
    float acc[32];
#pragma unroll
    for (int i = 0; i < 32; i++) acc[i] = bo;
#pragma unroll
    for (int c = 0; c < 6; c++) {
        float wv = sW[o*8 + c];
#pragma unroll
        for (int i = 0; i < 32; i++)
            acc[i] = fmaf(sIn[(pg*32 + i)*6 + c], wv, acc[i]);
    }
    float ls = 0.f, lq2 = 0.f;
    float* dst = &g_buf1[(size_t)tile*8192 + o*128 + pg*32];
#pragma unroll
    for (int i4 = 0; i4 < 8; i4++) {
        float4 v4 = make_float4(acc[i4*4+0], acc[i4*4+1], acc[i4*4+2], acc[i4*4+3]);
        ((float4*)dst)[i4] = v4;
        ls  += v4.x + v4.y + v4.z + v4.w;
        lq2 += v4.x*v4.x + v4.y*v4.y + v4.z*v4.z + v4.w*v4.w;
    }
    rs[pg][o] = ls; rq[pg][o] = lq2;
    __syncthreads();
    if (t < 64) {
        g_p1s[t*NT + tile] = rs[0][t] + rs[1][t] + rs[2][t] + rs[3][t];
        g_p1q[t*NT + tile] = rq[0][t] + rq[1][t] + rq[2][t] + rq[3][t];
    }
}

// ---------------------------------------------------------------------------
// Finalize BN stats (double precision), one block per channel.
// ---------------------------------------------------------------------------
__global__ __launch_bounds__(256) void finalize_kernel(const float* __restrict__ gma,
                                                       const float* __restrict__ bet,
                                                       int layer)
{
    const float* ps; const float* pq; float* sc; float* sh;
    if (layer == 0)      { ps = g_p1s; pq = g_p1q; sc = g_sc1; sh = g_sh1; }
    else if (layer == 1) { ps = g_p2s; pq = g_p2q; sc = g_sc2; sh = g_sh2; }
    else                 { ps = g_p3s; pq = g_p3q; sc = g_sc3; sh = g_sh3; }

    const int ch = blockIdx.x, t = threadIdx.x;
    __shared__ double sa[256], sb[256];
    double a = 0.0, b2 = 0.0;
    for (int i = t; i < NT; i += 256) {
        a  += (double)ps[ch*NT + i];
        b2 += (double)pq[ch*NT + i];
    }
    sa[t] = a; sb[t] = b2;
    __syncthreads();
    for (int off = 128; off > 0; off >>= 1) {
        if (t < off) { sa[t] += sa[t + off]; sb[t] += sb[t + off]; }
        __syncthreads();
    }
    if (t == 0) {
        const double n = (double)NPT;
        double mean = sa[0] / n;
        double var  = sb[0] / n - mean*mean;
        double s    = (double)gma[ch] / sqrt(var + 1e-5);
        sc[ch] = (float)s;
        sh[ch] = (float)((double)bet[ch] - mean*s);
    }
}

// ---------------------------------------------------------------------------
// 4) Layer2: BN1+ReLU on load, 64->64 matmul with 8x8 register tiles and
//    packed f32x2 FMA. Block = 128-pt tile, 128 threads (8x16 tile grid).
// ---------------------------------------------------------------------------
__global__ __launch_bounds__(128, 4) void layer2_kernel(const float* __restrict__ W2,
                                                        const float* __restrict__ b2)
{
    __shared__ __align__(16) float              sInT[32*128];   // [c][pt]
    __shared__ __align__(16) unsigned long long sWT2[32*64];    // [c][ch] dup pairs
    __shared__ float sS[64*16], sQ[64*16];

    const int t = threadIdx.x;
    const int tile = blockIdx.x;
    const int col = t & 15;          // point group: pts col*8 .. col*8+7
    const int row = t >> 4;          // channel group: ch row*8 .. row*8+7

    unsigned long long acc[8][4];
#pragma unroll
    for (int j = 0; j < 8; j++) {
        float bo = b2[row*8 + j];
        unsigned long long bp = pack2(bo, bo);
#pragma unroll
        for (int k = 0; k < 4; k++) acc[j][k] = bp;
    }

    const float* src = g_buf1 + (size_t)tile*8192;

    for (int kc = 0; kc < 64; kc += 32) {
        for (int idx = t; idx < 1024; idx += 128) {       // 32 rows * 32 float4
            int r = idx >> 5, p4 = idx & 31;
            int c = kc + r;
            float4 v = ((const float4*)(src + c*128))[p4];
            float s = g_sc1[c], h = g_sh1[c];
            float4 o4;
            o4.x = fmaxf(fmaf(v.x, s, h), 0.f);
            o4.y = fmaxf(fmaf(v.y, s, h), 0.f);
            o4.z = fmaxf(fmaf(v.z, s, h), 0.f);
            o4.w = fmaxf(fmaf(v.w, s, h), 0.f);
            ((float4*)(sInT + r*128))[p4] = o4;
        }
        for (int idx = t; idx < 2048; idx += 128) {       // 32 c * 64 ch
            int r = idx >> 6, o = idx & 63;
            float wv = W2[o*64 + kc + r];
            sWT2[r*64 + o] = pack2(wv, wv);
        }
        __syncthreads();
#pragma unroll 4
        for (int c = 0; c < 32; c++) {
            const ulonglong2* pa = (const ulonglong2*)&sInT[c*128 + col*8];
            ulonglong2 a0 = pa[0], a1 = pa[1];
            const ulonglong2* pw = (const ulonglong2*)&sWT2[c*64 + row*8];
            ulonglong2 w0 = pw[0], w1 = pw[1], w2 = pw[2], w3 = pw[3];
            unsigned long long av[4] = { a0.x, a0.y, a1.x, a1.y };
            unsigned long long wv[8] = { w0.x, w0.y, w1.x, w1.y, w2.x, w2.y, w3.x, w3.y };
#pragma unroll
            for (int j = 0; j < 8; j++)
#pragma unroll
                for (int k = 0; k < 4; k++)
                    acc[j][k] = fma2(av[k], wv[j], acc[j][k]);
        }
        __syncthreads();
    }

    float* dst = g_buf2 + (size_t)tile*8192 + col*8;
#pragma unroll
    for (int j = 0; j < 8; j++) {
        int ch = row*8 + j;
        ulonglong2 s0; s0.x = acc[j][0]; s0.y = acc[j][1];
        ulonglong2 s1; s1.x = acc[j][2]; s1.y = acc[j][3];
        ((ulonglong2*)(dst + ch*128))[0] = s0;
        ((ulonglong2*)(dst + ch*128))[1] = s1;
        float ls = 0.f, lq = 0.f;
#pragma unroll
        for (int k = 0; k < 4; k++) {
            float lo, hi; unpk(acc[j][k], lo, hi);
            ls += lo + hi; lq += lo*lo + hi*hi;
        }
        sS[ch*16 + col] = ls; sQ[ch*16 + col] = lq;
    }
    __syncthreads();
    if (t < 64) {
        float s = 0.f, q = 0.f;
#pragma unroll
        for (int cc = 0; cc < 16; cc++) { s += sS[t*16 + cc]; q += sQ[t*16 + cc]; }
        g_p2s[t*NT + tile] = s; g_p2q[t*NT + tile] = q;
    }
}

// ---------------------------------------------------------------------------
// 5) Layer3: BN2+ReLU on load, 64->128 matmul (8x8 tiles, f32x2), stats, and
//    FUSED max-over-k (per query, per channel) -> g_maxpre. No g_buf3.
//    Block = 128-pt tile (= 4 queries), 256 threads (16x16 tile grid).
// ---------------------------------------------------------------------------
__global__ __launch_bounds__(256, 2) void layer3_kernel(const float* __restrict__ W3,
                                                        const float* __restrict__ b3)
{
    __shared__ __align__(16) float              sInT[16*128];   // [c][pt]
    __shared__ __align__(16) unsigned long long sWT2[16*128];   // [c][ch] dup pairs
    __shared__ float sS[128*16], sQ[128*16];

    const int t = threadIdx.x;
    const int tile = blockIdx.x;
    const int col = t & 15;          // pts col*8 .. col*8+7 (all inside query col/4)
    const int row = t >> 4;          // ch row*8 .. row*8+7  (row 0..15 -> 128 ch)

    unsigned long long acc[8][4];
#pragma unroll
    for (int j = 0; j < 8; j++) {
        float bo = b3[row*8 + j];
        unsigned long long bp = pack2(bo, bo);
#pragma unroll
        for (int k = 0; k < 4; k++) acc[j][k] = bp;
    }

    const float* src = g_buf2 + (size_t)tile*8192;

    for (int kc = 0; kc < 64; kc += 16) {
        for (int idx = t; idx < 512; idx += 256) {        // 16 rows * 32 float4
            int r = idx >> 5, p4 = idx & 31;
            int c = kc + r;
            float4 v = ((const float4*)(src + c*128))[p4];
            float s = g_sc2[c], h = g_sh2[c];
            float4 o4;
            o4.x = fmaxf(fmaf(v.x, s, h), 0.f);
            o4.y = fmaxf(fmaf(v.y, s, h), 0.f);
            o4.z = fmaxf(fmaf(v.z, s, h), 0.f);
            o4.w = fmaxf(fmaf(v.w, s, h), 0.f);
            ((float4*)(sInT + r*128))[p4] = o4;
        }
        for (int idx = t; idx < 2048; idx += 256) {       // 16 c * 128 ch
            int r = idx >> 7, o = idx & 127;
            float wv = W3[o*64 + kc + r];
            sWT2[r*128 + o] = pack2(wv, wv);
        }
        __syncthreads();
#pragma unroll 4
        for (int c = 0; c < 16; c++) {
            const ulonglong2* pa = (const ulonglong2*)&sInT[c*128 + col*8];
            ulonglong2 a0 = pa[0], a1 = pa[1];
            const ulonglong2* pw = (const ulonglong2*)&sWT2[c*128 + row*8];
            ulonglong2 w0 = pw[0], w1 = pw[1], w2 = pw[2], w3 = pw[3];
            unsigned long long av[4] = { a0.x, a0.y, a1.x, a1.y };
            unsigned long long wv[8] = { w0.x, w0.y, w1.x, w1.y, w2.x, w2.y, w3.x, w3.y };
#pragma unroll
            for (int j = 0; j < 8; j++)
#pragma unroll
                for (int k = 0; k < 4; k++)
                    acc[j][k] = fma2(av[k], wv[j], acc[j][k]);
        }
        __syncthreads();
    }

    // stats
#pragma unroll
    for (int j = 0; j < 8; j++) {
        int ch = row*8 + j;
        float ls = 0.f, lq = 0.f;
#pragma unroll
        for (int k = 0; k < 4; k++) {
            float lo, hi; unpk(acc[j][k], lo, hi);
            ls += lo + hi; lq += lo*lo + hi*hi;
        }
        sS[ch*16 + col] = ls; sQ[ch*16 + col] = lq;
    }
    __syncthreads();
    if (t < 128) {
        float s = 0.f, q = 0.f;
#pragma unroll
        for (int cc = 0; cc < 16; cc++) { s += sS[t*16 + cc]; q += sQ[t*16 + cc]; }
        g_p3s[t*NT + tile] = s; g_p3q[t*NT + tile] = q;
    }
    __syncthreads();

    // per-thread max over its 8 points (all in one query), reuse sS
#pragma unroll
    for (int j = 0; j < 8; j++) {
        int ch = row*8 + j;
        float m = -3.0e38f;
#pragma unroll
        for (int k = 0; k < 4; k++) {
            float lo, hi; unpk(acc[j][k], lo, hi);
            m = fmaxf(m, fmaxf(lo, hi));
        }
        sS[ch*16 + col] = m;
    }
    __syncthreads();
    if (t < 128) {
#pragma unroll
        for (int qq = 0; qq < 4; qq++) {
            float m = sS[t*16 + qq*4 + 0];
            m = fmaxf(m, sS[t*16 + qq*4 + 1]);
            m = fmaxf(m, sS[t*16 + qq*4 + 2]);
            m = fmaxf(m, sS[t*16 + qq*4 + 3]);
            g_maxpre[(size_t)((tile<<2) + qq)*128 + t] = m;
        }
    }
}

// ---------------------------------------------------------------------------
// 6) Final: BN3+ReLU on the per-query maxima (scale>0 so max commutes exactly),
//    coalesced write of new_points.
// ---------------------------------------------------------------------------
__global__ __launch_bounds__(256) void maxfinal_kernel(float* __restrict__ out)
{
    const int gid = blockIdx.x * 256 + threadIdx.x;   // [0, B*128*1024)
    const int s = gid & 1023;
    const int rest = gid >> 10;
    const int o = rest & 127;
    const int b = rest >> 7;
    const int q = b*1024 + s;
    float v = g_maxpre[(size_t)q*128 + o];
    float r = fmaxf(fmaf(v, g_sc3[o], g_sh3[o]), 0.f);
    out[BB*3*SS + (size_t)b*C3*SS + o*SS + s] = r;
}

// ---------------------------------------------------------------------------
extern "C" void kernel_launch(void* const* d_in, const int* in_sizes, int n_in,
                              void* d_out, int out_size)
{
    const float* xyz = (const float*)d_in[0];
    const float* pts = (const float*)d_in[1];
    const float* W1  = (const float*)d_in[2];
    const float* b1  = (const float*)d_in[3];
    const float* g1  = (const float*)d_in[4];
    const float* be1 = (const float*)d_in[5];
    const float* W2  = (const float*)d_in[6];
    const float* b2  = (const float*)d_in[7];
    const float* g2  = (const float*)d_in[8];
    const float* be2 = (const float*)d_in[9];
    const float* W3  = (const float*)d_in[10];
    const float* b3  = (const float*)d_in[11];
    const float* g3  = (const float*)d_in[12];
    const float* be3 = (const float*)d_in[13];
    float* out = (float*)d_out;

    fps_kernel<<<BB, 256>>>(xyz, out);
    ballquery_kernel<<<(BB*SS*32)/256, 256>>>(xyz);
    layer1_kernel<<<NT, 256>>>(xyz, pts, W1, b1);
    finalize_kernel<<<C1, 256>>>(g1, be1, 0);
    layer2_kernel<<<NT, 128>>>(W2, b2);
    finalize_kernel<<<C2, 256>>>(g2, be2, 1);
    layer3_kernel<<<NT, 256>>>(W3, b3);
    finalize_kernel<<<C3, 256>>>(g3, be3, 2);
    maxfinal_kernel<<<(BB*SS*C3)/256, 256>>>(out);
}